// round 17
// baseline (speedup 1.0000x reference)
#include <cuda_runtime.h>
#include <cuda_bf16.h>

// CRF NLL, prob-domain. B=64, S=512, T=64 (START=62, END=63).
// R17 = R16 (warp-specialized: warps 0-1 compute the chain step, warps 2-3
//            stage emissions + compute the renorm during k=0, applied k=1)
//   + overflow fix: renorm scale biased by 2^-24 (exactly compensated via
//     ksum), restoring bf16 range headroom lost to the 2-step measure->apply
//     lag (peak exponent 10g-24 ~ 2^110 < 2^127).
//
// Inputs: d_in[0] feats f32 [B,S,T], d_in[1] transitions f32 [T,T],
//         d_in[2] mask i32 [B,S] (contiguous prefix), d_in[3] tags i32 [B,S]
// Output: f32 scalar sum_b (forward_b - gold_b)

#define B_    64
#define S_    512
#define T_    64
#define CHUNK 8
#define RBIAS 24

__device__ float g_vec[B_][2][T_];   // final chain vectors (fp32)
__device__ int   g_k[B_][2];         // renorm exponent sums
__device__ float g_gold[B_];
__device__ float g_res[B_];
__device__ int   g_pair[B_];         // per-batch arrival counters (init 0)
__device__ int   g_cnt = 0;          // completion counter

static __device__ __forceinline__ __nv_bfloat162 u2b(unsigned u) {
    return *(__nv_bfloat162*)&u;
}
static __device__ __forceinline__ __nv_bfloat16 pow2_bf16(int e) {
    unsigned short sb = (unsigned short)((e + 127) << 7);
    return *(__nv_bfloat16*)&sb;
}
// exponent (unbiased) of max over 64 bf16 values (8 uint4 broadcast loads)
static __device__ __forceinline__ int max_exp64(const unsigned* p) {
    const uint4* pv = (const uint4*)p;
    __nv_bfloat162 m0, m1, m2, m3;
    {
        uint4 u = pv[0];
        m0 = u2b(u.x); m1 = u2b(u.y); m2 = u2b(u.z); m3 = u2b(u.w);
    }
    #pragma unroll
    for (int i = 1; i < 8; ++i) {
        uint4 u = pv[i];
        m0 = __hmax2(m0, u2b(u.x));
        m1 = __hmax2(m1, u2b(u.y));
        m2 = __hmax2(m2, u2b(u.z));
        m3 = __hmax2(m3, u2b(u.w));
    }
    __nv_bfloat162 mm = __hmax2(__hmax2(m0, m1), __hmax2(m2, m3));
    __nv_bfloat16  mx = __hmax(__low2bfloat16(mm), __high2bfloat16(mm));
    unsigned short bits = *(unsigned short*)&mx;
    return (int)((bits >> 7) & 0xFF) - 127;
}

__global__ __launch_bounds__(128, 1) void crf_forward_kernel(
    const float* __restrict__ feats,
    const float* __restrict__ trans,
    const int*   __restrict__ mask,
    const int*   __restrict__ tags,
    float* __restrict__ out)
{
    __shared__ __align__(16) float    trans_sh[T_ * T_];
    __shared__ __align__(16) unsigned p_sh[2][T_ / 2];        // bf16 pairs
    __shared__ __align__(16) __nv_bfloat16 f_sh[2][CHUNK][T_]; // double-buffered
    __shared__ __nv_bfloat16 scale_sh;
    __shared__ float redg[4];
    __shared__ float redf[2];
    __shared__ int   redi[4];
    __shared__ int   sh_old;

    const int bid  = blockIdx.x;
    const int b    = bid >> 1;
    const int side = bid & 1;            // 0 = forward, 1 = backward
    const int tid  = threadIdx.x;
    const int lane = tid & 31;
    const int warp = tid >> 5;
    const bool is_compute = (tid < 64);  // warps 0-1 compute, 2-3 stage
    const int sid  = tid & 63;           // column index within role

    const float* fbp   = feats + (size_t)b * S_ * T_;
    const int*   maskb = mask  + b * S_;
    const int*   tagsb = tags  + b * S_;

    // ---- stage transitions (1024 float4 / 128 thr = 8 each) ----
    {
        const float4* t4 = (const float4*)trans;
        float4*       s4 = (float4*)trans_sh;
        #pragma unroll
        for (int i = 0; i < 8; ++i) s4[i * 128 + tid] = t4[i * 128 + tid];
    }
    // ---- length (all 128 threads) ----
    int lenp = 0;
    #pragma unroll
    for (int k = 0; k < 4; ++k) lenp += maskb[k * 128 + tid];
    #pragma unroll
    for (int o = 16; o; o >>= 1) lenp += __shfl_xor_sync(0xffffffffu, lenp, o);
    if (lane == 0) redi[warp] = lenp;
    __syncthreads();   // trans_sh + redi visible
    const int len = redi[0] + redi[1] + redi[2] + redi[3];

    // ---- gold path score (fwd CTA only; one-time, all threads) ----
    if (side == 0) {
        float g = 0.f;
        #pragma unroll
        for (int kk = 0; kk < 4; ++kk) {
            int s = kk * 128 + tid;
            if (s < len) {
                int tg = tagsb[s];
                int pv = s ? tagsb[s - 1] : (T_ - 2);
                g += fbp[s * T_ + tg] + trans_sh[pv * T_ + tg];
            }
        }
        if (tid == 0) g += trans_sh[tagsb[len - 1] * T_ + (T_ - 1)];
        #pragma unroll
        for (int o = 16; o; o >>= 1) g += __shfl_xor_sync(0xffffffffu, g, o);
        if (lane == 0) redg[warp] = g;
    }

    const int total  = len - 2;
    const int bsteps = total >> 1;
    const int fsteps = total - bsteps;
    const int steps  = side ? bsteps : fsteps;
    const int base   = side ? (len - 2) : 1;
    const int dir    = side ? -1 : 1;
    #define EMROW(s) (min(max(base + dir * (s), 0), S_ - 1))

    // ---- role-specific setup ----
    unsigned e2[32];      // compute only
    float    fr[CHUNK];   // staging only
    if (is_compute) {
        #pragma unroll
        for (int m = 0; m < 32; ++m) {
            float x, y;
            if (side == 0) {   // fwd: column E[i][j]
                x = __expf(trans_sh[(2 * m) * T_ + sid]);
                y = __expf(trans_sh[(2 * m + 1) * T_ + sid]);
            } else {           // bwd: row E[j][i]
                x = __expf(trans_sh[sid * T_ + 2 * m]);
                y = __expf(trans_sh[sid * T_ + 2 * m + 1]);
            }
            __nv_bfloat162 t = __floats2bfloat162_rn(x, y);
            e2[m] = *(unsigned*)&t;
        }
        // init chain state
        float v;
        if (side == 0)
            v = __expf(fbp[sid] + trans_sh[(T_ - 2) * T_ + sid]);
        else
            v = __expf(fbp[(len - 1) * T_ + sid] + trans_sh[sid * T_ + (T_ - 1)]);
        ((__nv_bfloat16*)p_sh[0])[sid] = __float2bfloat16(v);
    } else {
        // prologue: stage chunk 0; prefetch chunk 1
        #pragma unroll
        for (int k = 0; k < CHUNK; ++k)
            f_sh[0][k][sid] = __float2bfloat16(__expf(fbp[EMROW(k) * T_ + sid]));
        #pragma unroll
        for (int k = 0; k < CHUNK; ++k)
            fr[k] = fbp[EMROW(CHUNK + k) * T_ + sid];
    }
    __syncthreads();   // p_sh[0], f_sh[0], redg visible

    // ---- chain recurrence: warp-specialized, 1 barrier/step ----
    int n = 0, cur = 0, ksum = 0, fbuf = 0;

    while (n < steps) {
        const int  cnt       = min(CHUNK, steps - n);
        const bool do_renorm = (cnt > 1);

        #pragma unroll
        for (int k = 0; k < CHUNK; ++k) {
            if (k >= cnt) break;   // block-uniform
            if (is_compute) {
                __nv_bfloat16 sc;
                if (k == 1 && do_renorm) sc = scale_sh;   // staged at k=0
                __nv_bfloat16 fk = f_sh[fbuf][k][sid];
                const uint4* pp = (const uint4*)p_sh[cur];
                __nv_bfloat162 a0, a1, a2, a3;
                {
                    uint4 u = pp[0];
                    a0 = __hmul2(u2b(u.x), u2b(e2[0]));
                    a1 = __hmul2(u2b(u.y), u2b(e2[1]));
                    a2 = __hmul2(u2b(u.z), u2b(e2[2]));
                    a3 = __hmul2(u2b(u.w), u2b(e2[3]));
                }
                #pragma unroll
                for (int m = 1; m < 8; ++m) {
                    uint4 u = pp[m];
                    a0 = __hfma2(u2b(u.x), u2b(e2[4 * m + 0]), a0);
                    a1 = __hfma2(u2b(u.y), u2b(e2[4 * m + 1]), a1);
                    a2 = __hfma2(u2b(u.z), u2b(e2[4 * m + 2]), a2);
                    a3 = __hfma2(u2b(u.w), u2b(e2[4 * m + 3]), a3);
                }
                __nv_bfloat162 s = __hadd2(__hadd2(a0, a1), __hadd2(a2, a3));
                __nv_bfloat16  h = __hadd(__low2bfloat16(s), __high2bfloat16(s));
                __nv_bfloat16  q = __hmul(h, fk);
                if (k == 1 && do_renorm) q = __hmul(q, sc);
                ((__nv_bfloat16*)p_sh[cur ^ 1])[sid] = q;
            } else {
                if (k == 0 && do_renorm) {
                    // renorm: p_sh[cur] stable during k=0 (k=0 writes cur^1)
                    // biased scale 2^-(ke+RBIAS): headroom for the 2-step
                    // measure->apply lag; exactly compensated via ksum.
                    int ke = max_exp64(p_sh[cur]) + RBIAS;
                    ksum += ke;
                    if (tid == 64) scale_sh = pow2_bf16(-ke);
                }
                // stage row k of next chunk; refill fr[k] with chunk n+2
                f_sh[fbuf ^ 1][k][sid] = __float2bfloat16(__expf(fr[k]));
                fr[k] = fbp[EMROW(n + 2 * CHUNK + k) * T_ + sid];
            }
            __syncthreads();
            cur ^= 1;
        }
        fbuf ^= 1;
        n += CHUNK;
    }
    #undef EMROW

    // ---- publish chain result ----
    if (is_compute)
        g_vec[b][side][sid] =
            __bfloat162float(((const __nv_bfloat16*)p_sh[cur])[sid]);
    if (tid == 64) g_k[b][side] = ksum;
    if (tid == 0 && side == 0)
        g_gold[b] = redg[0] + redg[1] + redg[2] + redg[3];
    __threadfence();
    __syncthreads();
    if (tid == 0) sh_old = atomicAdd(&g_pair[b], 1);
    __syncthreads();
    if (sh_old == 0) return;   // first arriver of the pair

    // ---- second arriver: stitch Z = (alpha_M E) . w_{M+1} (fp32, one-time) ----
    __threadfence();
    if (is_compute) {
        const volatile float* aF = g_vec[b][0];
        const volatile float* wB = g_vec[b][1];
        float v = 0.f;
        #pragma unroll
        for (int i = 0; i < T_; ++i)
            v = fmaf(aF[i], __expf(trans_sh[i * T_ + sid]), v);
        float z = v * wB[sid];
        #pragma unroll
        for (int o = 16; o; o >>= 1) z += __shfl_xor_sync(0xffffffffu, z, o);
        if (lane == 0) redf[warp] = z;
    }
    __syncthreads();
    if (tid == 0) {
        float tot = redf[0] + redf[1];
        int ksA = *((volatile int*)&g_k[b][0]);
        int ksB = *((volatile int*)&g_k[b][1]);
        float forward = (float)(ksA + ksB) * 0.69314718055994531f + __logf(tot);
        float gold = *((volatile float*)&g_gold[b]);
        g_res[b] = forward - gold;
        g_pair[b] = 0;   // reset for next graph replay
        __threadfence();
        int done = atomicAdd(&g_cnt, 1);
        if (done == B_ - 1) {
            __threadfence();
            float acc = 0.f;
            #pragma unroll
            for (int i = 0; i < B_; ++i)
                acc += *((volatile float*)&g_res[i]);
            out[0] = acc;
            g_cnt = 0;
        }
    }
}

extern "C" void kernel_launch(void* const* d_in, const int* in_sizes, int n_in,
                              void* d_out, int out_size)
{
    const float* feats = (const float*)d_in[0];
    const float* trans = (const float*)d_in[1];
    const int*   mask  = (const int*)d_in[2];
    const int*   tags  = (const int*)d_in[3];
    float* out = (float*)d_out;

    crf_forward_kernel<<<2 * B_, 128>>>(feats, trans, mask, tags, out);
}